// round 10
// baseline (speedup 1.0000x reference)
#include <cuda_runtime.h>

// AdderNet: out[n,h,w,f] = sum_{dh,dw,c} |Xpad[n,h+dh-1,w+dw-1,c] - F[f,dh,dw,c]|
// X [8,32,32,32] f32 NHWC, F [64,3,3,32] f32, out [8,32,32,64] f32.
//
// R10: 4px x 1f tile -> 4 outputs/thread -> 4096 warps (27/SM) AND low load
// ratio (9 LDS per 96 math). Filters in smem TRANSPOSED [tap][c4][fg16] so the
// warp's 4 fg lanes hit 64B contiguous (1 wavefront, 8-way bcast). X smem
// swizzle s = r*9+q (wp = 4q+r): 6 x-loads 128B-contiguous. Block 128 =
// wq(8) x fg(16), grid (256 nh, 4 fq) = 1024 CTAs, 7 CTA/SM (32.2KB smem).

#define XS_F4 (3 * 8 * 36)          // 864 float4
#define FS_F4 (72 * 16)             // 1152 float4: [tap 0..71][fg 0..15]
#define SMEM_BYTES ((XS_F4 + FS_F4) * 16)   // 32,256 B

typedef unsigned long long u64;

__device__ __forceinline__ u64 ffma2(u64 a, u64 b, u64 c) {
    u64 r;
    asm("fma.rn.f32x2 %0, %1, %2, %3;" : "=l"(r) : "l"(a), "l"(b), "l"(c));
    return r;
}
__device__ __forceinline__ u64 fadd2(u64 a, u64 b) {
    u64 r;
    asm("add.rn.f32x2 %0, %1, %2;" : "=l"(r) : "l"(a), "l"(b));
    return r;
}

// acc (ulonglong2) += | x - t | over one 16B chunk (4 channels)
#define UPD2(acc, t, xa)                                              \
    (acc).x = fadd2((acc).x, ffma2((t).x, NEG1, (xa).x) & ABSM);      \
    (acc).y = fadd2((acc).y, ffma2((t).y, NEG1, (xa).y) & ABSM)

__global__ __launch_bounds__(128, 7)
void adder_layer_kernel(const float* __restrict__ X,
                        const float* __restrict__ Fw,
                        float* __restrict__ out) {
    extern __shared__ __align__(16) float4 smem4[];
    float4* Xs4 = smem4;              // [(dh*8 + c4)*36 + s], s = r*9+q, wp = 4q+r
    float4* Fs4 = smem4 + XS_F4;      // [tap*16 + fg], tap = dh*24 + dw*8 + c4

    const int tid = threadIdx.x;
    const int nh = blockIdx.x;        // n*32 + h
    const int fbase = blockIdx.y * 16;
    const int n = nh >> 5;
    const int h = nh & 31;

    // ---- Filter fill, transposed: Fs4[tap*16 + fg] = Fg4[(fbase+fg)*72 + tap] ----
    const float4* Fg4 = reinterpret_cast<const float4*>(Fw);
    for (int i = tid; i < FS_F4; i += 128) {
        int fg = i & 15;
        int tap = i >> 4;             // 0..71
        Fs4[tap * 16 + fg] = Fg4[(fbase + fg) * 72 + tap];
    }

    // ---- X fill: 3 rows, swizzled, zero-padded ----
    const float4* Xg4 = reinterpret_cast<const float4*>(X);
    for (int i = tid; i < XS_F4; i += 128) {
        int c4 = i & 7;
        int t = i >> 3;
        int s = t % 36;
        int dh = t / 36;
        int q = s % 9, r = s / 9;
        int wp = 4 * q + r;
        int row = h - 1 + dh;
        int w = wp - 1;
        float4 v = make_float4(0.f, 0.f, 0.f, 0.f);
        if (row >= 0 && row < 32 && w >= 0 && w < 32)
            v = Xg4[(((n * 32) + row) * 32 + w) * 8 + c4];
        Xs4[(dh * 8 + c4) * 36 + s] = v;
    }
    __syncthreads();

    const int wq = tid & 7;           // pixels w = 4wq .. 4wq+3
    const int fg = tid >> 3;          // 0..15 -> filter fbase + fg

    const u64 NEG1 = 0xBF800000BF800000ULL;
    const u64 ABSM = 0x7FFFFFFF7FFFFFFFULL;

    ulonglong2 acc0 = {0ull, 0ull}, acc1 = {0ull, 0ull};
    ulonglong2 acc2 = {0ull, 0ull}, acc3 = {0ull, 0ull};

    const ulonglong2* Xu = reinterpret_cast<const ulonglong2*>(Xs4);
    const ulonglong2* Fu = reinterpret_cast<const ulonglong2*>(Fs4) + fg;

    #pragma unroll 2
    for (int kk = 0; kk < 24; kk++) {
        const int dh = kk >> 3;
        const int c4 = kk & 7;

        // filter taps: tap = dh*24 + dw*8 + c4, consecutive dw at +128 f4... (+8*16)
        const ulonglong2* fr = Fu + (dh * 24 + c4) * 16;
        ulonglong2 t0 = fr[0];        // dw=0   (4 fg lanes: 64B contiguous)
        ulonglong2 t1 = fr[128];      // dw=1
        ulonglong2 t2 = fr[256];      // dw=2

        // x: 4 channels at wp = 4wq + k, k = 0..5 (128B contiguous across wq)
        const ulonglong2* xr = Xu + kk * 36 + wq;
        ulonglong2 x0 = xr[0];
        ulonglong2 x1 = xr[9];
        ulonglong2 x2 = xr[18];
        ulonglong2 x3 = xr[27];
        ulonglong2 x4 = xr[1];
        ulonglong2 x5 = xr[10];

        // pixel p uses x[p+dw]
        UPD2(acc0, t0, x0); UPD2(acc0, t1, x1); UPD2(acc0, t2, x2);
        UPD2(acc1, t0, x1); UPD2(acc1, t1, x2); UPD2(acc1, t2, x3);
        UPD2(acc2, t0, x2); UPD2(acc2, t1, x3); UPD2(acc2, t2, x4);
        UPD2(acc3, t0, x3); UPD2(acc3, t1, x4); UPD2(acc3, t2, x5);
    }

    // ---- Epilogue: reduce 4 channel-lanes per pixel, scalar store ----
    float* obase = out + ((nh * 32) + 4 * wq) * 64 + fbase + fg;
    {
        u64 s = fadd2(acc0.x, acc0.y);
        obase[0] = __uint_as_float((unsigned)s) + __uint_as_float((unsigned)(s >> 32));
    }
    {
        u64 s = fadd2(acc1.x, acc1.y);
        obase[64] = __uint_as_float((unsigned)s) + __uint_as_float((unsigned)(s >> 32));
    }
    {
        u64 s = fadd2(acc2.x, acc2.y);
        obase[128] = __uint_as_float((unsigned)s) + __uint_as_float((unsigned)(s >> 32));
    }
    {
        u64 s = fadd2(acc3.x, acc3.y);
        obase[192] = __uint_as_float((unsigned)s) + __uint_as_float((unsigned)(s >> 32));
    }
}

extern "C" void kernel_launch(void* const* d_in, const int* in_sizes, int n_in,
                              void* d_out, int out_size) {
    const float* X = (const float*)d_in[0];
    const float* Fw = (const float*)d_in[1];
    float* out = (float*)d_out;

    cudaFuncSetAttribute(adder_layer_kernel,
                         cudaFuncAttributeMaxDynamicSharedMemorySize, SMEM_BYTES);
    dim3 grid(256, 4);
    adder_layer_kernel<<<grid, 128, SMEM_BYTES>>>(X, Fw, out);
}

// round 11
// speedup vs baseline: 1.3401x; 1.3401x over previous
#include <cuda_runtime.h>
#include <cuda_fp16.h>

// AdderNet: out[n,h,w,f] = sum_{dh,dw,c} |Xpad[n,h+dh-1,w+dw-1,c] - F[f,dh,dw,c]|
// X [8,32,32,32] f32 NHWC, F [64,3,3,32] f32, out [8,32,32,64] f32.
//
// R11: fp16 diff+abs+short-accumulate (hsub2/habs2/hadd2, <=1.5 instr/elem vs
// 2.0 for fp32-packed), fp32 flush every kk (12 terms/lane -> rel err ~2e-4).
// fp16 smem halves load traffic: 16B chunk = 8 channels, kk loop = 12 iters.
// Grid (256 nh, 4 fq), block 64 = wq(8) x fp(8); thread 4px x 2f.
// X swizzle s = r*9+q (wp = 4q+r): x-loads 128B-contiguous. Filter stride 37
// chunks (pair stride 1184B % 128 = 32) -> conflict-free.

#define XS_CH (3 * 4 * 36)          // 432 chunks: [(dh*4+c8)*36 + s]
#define FSTRIDE 37                  // padded chunks per filter
#define FS_CH (16 * FSTRIDE)        // 592 chunks: [f*37 + (dh*3+dw)*4 + c8]
#define SMEM_BYTES ((XS_CH + FS_CH) * 16)   // 16,384 B

struct __align__(16) H2x4 { __half2 a, b, c, d; };

__device__ __forceinline__ H2x4 cvt_chunk(float4 lo, float4 hi) {
    H2x4 r;
    r.a = __float22half2_rn(make_float2(lo.x, lo.y));
    r.b = __float22half2_rn(make_float2(lo.z, lo.w));
    r.c = __float22half2_rn(make_float2(hi.x, hi.y));
    r.d = __float22half2_rn(make_float2(hi.z, hi.w));
    return r;
}

// L1 distance over 24 terms (3 taps x 8 channels), fp16 pair accumulator.
__device__ __forceinline__ __half2 l1_24(
    const H2x4& xa, const H2x4& xb, const H2x4& xc,
    const H2x4& f0, const H2x4& f1, const H2x4& f2) {
    __half2 s = __habs2(__hsub2(xa.a, f0.a));
    s = __hadd2(s, __habs2(__hsub2(xa.b, f0.b)));
    s = __hadd2(s, __habs2(__hsub2(xa.c, f0.c)));
    s = __hadd2(s, __habs2(__hsub2(xa.d, f0.d)));
    s = __hadd2(s, __habs2(__hsub2(xb.a, f1.a)));
    s = __hadd2(s, __habs2(__hsub2(xb.b, f1.b)));
    s = __hadd2(s, __habs2(__hsub2(xb.c, f1.c)));
    s = __hadd2(s, __habs2(__hsub2(xb.d, f1.d)));
    s = __hadd2(s, __habs2(__hsub2(xc.a, f2.a)));
    s = __hadd2(s, __habs2(__hsub2(xc.b, f2.b)));
    s = __hadd2(s, __habs2(__hsub2(xc.c, f2.c)));
    s = __hadd2(s, __habs2(__hsub2(xc.d, f2.d)));
    return s;
}

__global__ __launch_bounds__(64, 8)
void adder_layer_kernel(const float* __restrict__ X,
                        const float* __restrict__ Fw,
                        float* __restrict__ out) {
    extern __shared__ __align__(16) H2x4 smem[];
    H2x4* Xs = smem;                  // [(dh*4 + c8)*36 + s], s = r*9+q, wp = 4q+r
    H2x4* Fs = smem + XS_CH;          // [fl*37 + (dh*3+dw)*4 + c8]

    const int tid = threadIdx.x;
    const int nh = blockIdx.x;        // n*32 + h
    const int fbase = blockIdx.y * 16;
    const int n = nh >> 5;
    const int h = nh & 31;

    const float4* Xg4 = reinterpret_cast<const float4*>(X);
    const float4* Fg4 = reinterpret_cast<const float4*>(Fw);

    // ---- Filter fill: fp32 -> fp16 chunks (8 channels each) ----
    for (int i = tid; i < 16 * 36; i += 64) {
        int fl = i / 36;
        int j = i - fl * 36;          // (dh*3+dw)*4 + c8
        int g = ((fbase + fl) * 36 + j) * 2;
        Fs[fl * FSTRIDE + j] = cvt_chunk(Fg4[g], Fg4[g + 1]);
    }

    // ---- X fill: 3 rows, swizzled, zero-padded, fp32 -> fp16 ----
    for (int i = tid; i < XS_CH; i += 64) {
        int c8 = i & 3;
        int t = i >> 2;
        int s = t % 36;
        int dh = t / 36;
        int q = s % 9, r = s / 9;
        int wp = 4 * q + r;
        int row = h - 1 + dh;
        int w = wp - 1;
        H2x4 v;
        if (row >= 0 && row < 32 && w >= 0 && w < 32) {
            int g = ((((n * 32) + row) * 32 + w) * 8 + c8 * 2);
            v = cvt_chunk(Xg4[g], Xg4[g + 1]);
        } else {
            __half2 z = __float2half2_rn(0.f);
            v.a = z; v.b = z; v.c = z; v.d = z;
        }
        Xs[(dh * 4 + c8) * 36 + s] = v;
    }
    __syncthreads();

    const int wq = tid & 7;           // pixels w = 4wq .. 4wq+3
    const int fp = tid >> 3;          // 0..7 -> filters fbase+2fp, fbase+2fp+1

    float2 accE[4], accO[4];          // [pixel], fp32 flush targets
    #pragma unroll
    for (int p = 0; p < 4; p++) {
        accE[p] = make_float2(0.f, 0.f);
        accO[p] = make_float2(0.f, 0.f);
    }

    const H2x4* Fb0 = Fs + (2 * fp) * FSTRIDE;    // filter even
    const H2x4* Fb1 = Fb0 + FSTRIDE;              // filter odd

    #pragma unroll 1
    for (int kk = 0; kk < 12; kk++) {             // kk = dh*4 + c8
        const int dh = kk >> 2;
        const int c8 = kk & 3;
        const int j0 = dh * 12 + c8;              // tap dw=0; dw steps of +4

        // x: 8 channels at wp = 4wq + k, k = 0..5 (contiguous across wq lanes)
        const H2x4* xr = Xs + kk * 36 + wq;
        H2x4 x0 = xr[0];
        H2x4 x1 = xr[9];
        H2x4 x2 = xr[18];
        H2x4 x3 = xr[27];
        H2x4 x4 = xr[1];
        H2x4 x5 = xr[10];

        // filter taps, 2 filters x 3 dw (4-lane 32B-spread broadcast)
        H2x4 e0 = Fb0[j0], e1 = Fb0[j0 + 4], e2 = Fb0[j0 + 8];
        H2x4 o0 = Fb1[j0], o1 = Fb1[j0 + 4], o2 = Fb1[j0 + 8];

        // per pixel p: taps see x[p], x[p+1], x[p+2]; flush fp16 sums to fp32
        {
            float2 t = __half22float2(l1_24(x0, x1, x2, e0, e1, e2));
            accE[0].x += t.x; accE[0].y += t.y;
            t = __half22float2(l1_24(x0, x1, x2, o0, o1, o2));
            accO[0].x += t.x; accO[0].y += t.y;
        }
        {
            float2 t = __half22float2(l1_24(x1, x2, x3, e0, e1, e2));
            accE[1].x += t.x; accE[1].y += t.y;
            t = __half22float2(l1_24(x1, x2, x3, o0, o1, o2));
            accO[1].x += t.x; accO[1].y += t.y;
        }
        {
            float2 t = __half22float2(l1_24(x2, x3, x4, e0, e1, e2));
            accE[2].x += t.x; accE[2].y += t.y;
            t = __half22float2(l1_24(x2, x3, x4, o0, o1, o2));
            accO[2].x += t.x; accO[2].y += t.y;
        }
        {
            float2 t = __half22float2(l1_24(x3, x4, x5, e0, e1, e2));
            accE[3].x += t.x; accE[3].y += t.y;
            t = __half22float2(l1_24(x3, x4, x5, o0, o1, o2));
            accO[3].x += t.x; accO[3].y += t.y;
        }
    }

    // ---- Epilogue: combine lanes, store float2 (2 filters) per pixel ----
    #pragma unroll
    for (int p = 0; p < 4; p++) {
        float e = accE[p].x + accE[p].y;
        float o = accO[p].x + accO[p].y;
        *reinterpret_cast<float2*>(
            out + ((nh * 32) + 4 * wq + p) * 64 + fbase + 2 * fp) = make_float2(e, o);
    }
}

extern "C" void kernel_launch(void* const* d_in, const int* in_sizes, int n_in,
                              void* d_out, int out_size) {
    const float* X = (const float*)d_in[0];
    const float* Fw = (const float*)d_in[1];
    float* out = (float*)d_out;

    cudaFuncSetAttribute(adder_layer_kernel,
                         cudaFuncAttributeMaxDynamicSharedMemorySize, SMEM_BYTES);
    dim3 grid(256, 4);
    adder_layer_kernel<<<grid, 64, SMEM_BYTES>>>(X, Fw, out);
}

// round 12
// speedup vs baseline: 1.4804x; 1.1047x over previous
#include <cuda_runtime.h>
#include <cuda_fp16.h>

// AdderNet: out[n,h,w,f] = sum_{dh,dw,c} |Xpad[n,h+dh-1,w+dw-1,c] - F[f,dh,dw,c]|
// X [8,32,32,32] f32 NHWC, F [64,3,3,32] f32, out [8,32,32,64] f32.
//
// R12: fp16 core (R11 math, rel_err ~1e-4) restructured for latency hiding:
//  - 4px x 1f tile -> 4096 warps (27/SM, was 10)
//  - tree-reduced HADD2 (depth 4, was 12) to shorten the dependency chain
//  - block 128 = wq(8) x fg(16), grid (256 nh, 4 fq) = 1024 CTAs
// X smem swizzle s = r*9+q (wp = 4q+r): x-loads 128B-contiguous across wq.
// Filters [f][tap] stride 37 chunks -> 4 distinct 16B lines/warp, bank-clean.

#define XS_CH (3 * 4 * 36)          // 432 chunks (16B = 8 channels fp16)
#define FSTRIDE 37
#define FS_CH (16 * FSTRIDE)        // 592 chunks
#define SMEM_BYTES ((XS_CH + FS_CH) * 16)   // 16,384 B

struct __align__(16) H2x4 { __half2 a, b, c, d; };

__device__ __forceinline__ H2x4 cvt_chunk(float4 lo, float4 hi) {
    H2x4 r;
    r.a = __float22half2_rn(make_float2(lo.x, lo.y));
    r.b = __float22half2_rn(make_float2(lo.z, lo.w));
    r.c = __float22half2_rn(make_float2(hi.x, hi.y));
    r.d = __float22half2_rn(make_float2(hi.z, hi.w));
    return r;
}

// L1 distance over 24 terms (3 taps x 8 ch), TREE-reduced fp16 pair sum.
__device__ __forceinline__ __half2 l1_24(
    const H2x4& xa, const H2x4& xb, const H2x4& xc,
    const H2x4& f0, const H2x4& f1, const H2x4& f2) {
    __half2 t0 = __habs2(__hsub2(xa.a, f0.a));
    __half2 t1 = __habs2(__hsub2(xa.b, f0.b));
    __half2 t2 = __habs2(__hsub2(xa.c, f0.c));
    __half2 t3 = __habs2(__hsub2(xa.d, f0.d));
    __half2 t4 = __habs2(__hsub2(xb.a, f1.a));
    __half2 t5 = __habs2(__hsub2(xb.b, f1.b));
    __half2 t6 = __habs2(__hsub2(xb.c, f1.c));
    __half2 t7 = __habs2(__hsub2(xb.d, f1.d));
    __half2 t8 = __habs2(__hsub2(xc.a, f2.a));
    __half2 t9 = __habs2(__hsub2(xc.b, f2.b));
    __half2 ta = __habs2(__hsub2(xc.c, f2.c));
    __half2 tb = __habs2(__hsub2(xc.d, f2.d));
    __half2 u0 = __hadd2(t0, t1);
    __half2 u1 = __hadd2(t2, t3);
    __half2 u2 = __hadd2(t4, t5);
    __half2 u3 = __hadd2(t6, t7);
    __half2 u4 = __hadd2(t8, t9);
    __half2 u5 = __hadd2(ta, tb);
    __half2 v0 = __hadd2(u0, u1);
    __half2 v1 = __hadd2(u2, u3);
    __half2 v2 = __hadd2(u4, u5);
    return __hadd2(__hadd2(v0, v1), v2);
}

__global__ __launch_bounds__(128, 7)
void adder_layer_kernel(const float* __restrict__ X,
                        const float* __restrict__ Fw,
                        float* __restrict__ out) {
    extern __shared__ __align__(16) H2x4 smem[];
    H2x4* Xs = smem;                  // [(dh*4 + c8)*36 + s], s = r*9+q, wp = 4q+r
    H2x4* Fs = smem + XS_CH;          // [fl*37 + (dh*3+dw)*4 + c8]

    const int tid = threadIdx.x;
    const int nh = blockIdx.x;        // n*32 + h
    const int fbase = blockIdx.y * 16;
    const int n = nh >> 5;
    const int h = nh & 31;

    const float4* Xg4 = reinterpret_cast<const float4*>(X);
    const float4* Fg4 = reinterpret_cast<const float4*>(Fw);

    // ---- Filter fill: fp32 -> fp16 chunks ----
    for (int i = tid; i < 16 * 36; i += 128) {
        int fl = i / 36;
        int j = i - fl * 36;          // (dh*3+dw)*4 + c8
        int g = ((fbase + fl) * 36 + j) * 2;
        Fs[fl * FSTRIDE + j] = cvt_chunk(Fg4[g], Fg4[g + 1]);
    }

    // ---- X fill: 3 rows, swizzled, zero-padded, fp32 -> fp16 ----
    for (int i = tid; i < XS_CH; i += 128) {
        int c8 = i & 3;
        int t = i >> 2;
        int s = t % 36;
        int dh = t / 36;
        int q = s % 9, r = s / 9;
        int wp = 4 * q + r;
        int row = h - 1 + dh;
        int w = wp - 1;
        H2x4 v;
        if (row >= 0 && row < 32 && w >= 0 && w < 32) {
            int g = ((((n * 32) + row) * 32 + w) * 8 + c8 * 2);
            v = cvt_chunk(Xg4[g], Xg4[g + 1]);
        } else {
            __half2 z = __float2half2_rn(0.f);
            v.a = z; v.b = z; v.c = z; v.d = z;
        }
        Xs[(dh * 4 + c8) * 36 + s] = v;
    }
    __syncthreads();

    const int wq = tid & 7;           // pixels w = 4wq .. 4wq+3
    const int fg = tid >> 3;          // 0..15 -> filter fbase + fg

    float2 acc[4];
    #pragma unroll
    for (int p = 0; p < 4; p++) acc[p] = make_float2(0.f, 0.f);

    const H2x4* Fb = Fs + fg * FSTRIDE;

    #pragma unroll 2
    for (int kk = 0; kk < 12; kk++) {             // kk = dh*4 + c8
        const int dh = kk >> 2;
        const int c8 = kk & 3;
        const int j0 = dh * 12 + c8;              // tap dw=0; dw steps +4

        // x: 8 channels at wp = 4wq + k, k = 0..5
        const H2x4* xr = Xs + kk * 36 + wq;
        H2x4 x0 = xr[0];
        H2x4 x1 = xr[9];
        H2x4 x2 = xr[18];
        H2x4 x3 = xr[27];
        H2x4 x4 = xr[1];
        H2x4 x5 = xr[10];

        // filter taps for this filter: 3 dw
        H2x4 f0 = Fb[j0], f1 = Fb[j0 + 4], f2 = Fb[j0 + 8];

        // per pixel p: taps see x[p], x[p+1], x[p+2]; fp32 flush each kk
        {
            float2 t = __half22float2(l1_24(x0, x1, x2, f0, f1, f2));
            acc[0].x += t.x; acc[0].y += t.y;
        }
        {
            float2 t = __half22float2(l1_24(x1, x2, x3, f0, f1, f2));
            acc[1].x += t.x; acc[1].y += t.y;
        }
        {
            float2 t = __half22float2(l1_24(x2, x3, x4, f0, f1, f2));
            acc[2].x += t.x; acc[2].y += t.y;
        }
        {
            float2 t = __half22float2(l1_24(x3, x4, x5, f0, f1, f2));
            acc[3].x += t.x; acc[3].y += t.y;
        }
    }

    // ---- Epilogue: combine packed lanes, scalar store per pixel ----
    float* obase = out + ((nh * 32) + 4 * wq) * 64 + fbase + fg;
    obase[0]   = acc[0].x + acc[0].y;
    obase[64]  = acc[1].x + acc[1].y;
    obase[128] = acc[2].x + acc[2].y;
    obase[192] = acc[3].x + acc[3].y;
}

extern "C" void kernel_launch(void* const* d_in, const int* in_sizes, int n_in,
                              void* d_out, int out_size) {
    const float* X = (const float*)d_in[0];
    const float* Fw = (const float*)d_in[1];
    float* out = (float*)d_out;

    cudaFuncSetAttribute(adder_layer_kernel,
                         cudaFuncAttributeMaxDynamicSharedMemorySize, SMEM_BYTES);
    dim3 grid(256, 4);
    adder_layer_kernel<<<grid, 128, SMEM_BYTES>>>(X, Fw, out);
}

// round 13
// speedup vs baseline: 1.5028x; 1.0152x over previous
#include <cuda_runtime.h>
#include <cuda_fp16.h>

// AdderNet: out[n,h,w,f] = sum_{dh,dw,c} |Xpad[n,h+dh-1,w+dw-1,c] - F[f,dh,dw,c]|
// X [8,32,32,32] f32 NHWC, F [64,3,3,32] f32, out [8,32,32,64] f32.
//
// R13: R12 fp16 core with overhead shaved:
//  - fp16 accumulation across each dh group (4 kk, 48 terms), fp32 flush 3x
//    total (was 12x) -> rel_err ~2e-4, within 1e-3.
//  - kk loop fully unrolled: immediate LDS offsets, no loop/index math.
// Tile 4px x 1f, block 128 = wq(8) x fg(16), grid (256 nh, 4 fq).
// X smem swizzle s = r*9+q (wp = 4q+r); filter stride 37 chunks.

#define XS_CH (3 * 4 * 36)          // 432 chunks (16B = 8 channels fp16)
#define FSTRIDE 37
#define FS_CH (16 * FSTRIDE)        // 592 chunks
#define SMEM_BYTES ((XS_CH + FS_CH) * 16)   // 16,384 B

struct __align__(16) H2x4 { __half2 a, b, c, d; };

__device__ __forceinline__ H2x4 cvt_chunk(float4 lo, float4 hi) {
    H2x4 r;
    r.a = __float22half2_rn(make_float2(lo.x, lo.y));
    r.b = __float22half2_rn(make_float2(lo.z, lo.w));
    r.c = __float22half2_rn(make_float2(hi.x, hi.y));
    r.d = __float22half2_rn(make_float2(hi.z, hi.w));
    return r;
}

// L1 distance over 24 terms (3 taps x 8 ch), tree-reduced fp16 pair sum.
__device__ __forceinline__ __half2 l1_24(
    const H2x4& xa, const H2x4& xb, const H2x4& xc,
    const H2x4& f0, const H2x4& f1, const H2x4& f2) {
    __half2 t0 = __habs2(__hsub2(xa.a, f0.a));
    __half2 t1 = __habs2(__hsub2(xa.b, f0.b));
    __half2 t2 = __habs2(__hsub2(xa.c, f0.c));
    __half2 t3 = __habs2(__hsub2(xa.d, f0.d));
    __half2 t4 = __habs2(__hsub2(xb.a, f1.a));
    __half2 t5 = __habs2(__hsub2(xb.b, f1.b));
    __half2 t6 = __habs2(__hsub2(xb.c, f1.c));
    __half2 t7 = __habs2(__hsub2(xb.d, f1.d));
    __half2 t8 = __habs2(__hsub2(xc.a, f2.a));
    __half2 t9 = __habs2(__hsub2(xc.b, f2.b));
    __half2 ta = __habs2(__hsub2(xc.c, f2.c));
    __half2 tb = __habs2(__hsub2(xc.d, f2.d));
    __half2 u0 = __hadd2(t0, t1);
    __half2 u1 = __hadd2(t2, t3);
    __half2 u2 = __hadd2(t4, t5);
    __half2 u3 = __hadd2(t6, t7);
    __half2 u4 = __hadd2(t8, t9);
    __half2 u5 = __hadd2(ta, tb);
    __half2 v0 = __hadd2(u0, u1);
    __half2 v1 = __hadd2(u2, u3);
    __half2 v2 = __hadd2(u4, u5);
    return __hadd2(__hadd2(v0, v1), v2);
}

__global__ __launch_bounds__(128, 7)
void adder_layer_kernel(const float* __restrict__ X,
                        const float* __restrict__ Fw,
                        float* __restrict__ out) {
    extern __shared__ __align__(16) H2x4 smem[];
    H2x4* Xs = smem;                  // [(dh*4 + c8)*36 + s], s = r*9+q, wp = 4q+r
    H2x4* Fs = smem + XS_CH;          // [fl*37 + (dh*3+dw)*4 + c8]

    const int tid = threadIdx.x;
    const int nh = blockIdx.x;        // n*32 + h
    const int fbase = blockIdx.y * 16;
    const int n = nh >> 5;
    const int h = nh & 31;

    const float4* Xg4 = reinterpret_cast<const float4*>(X);
    const float4* Fg4 = reinterpret_cast<const float4*>(Fw);

    // ---- Filter fill: fp32 -> fp16 chunks ----
    for (int i = tid; i < 16 * 36; i += 128) {
        int fl = i / 36;
        int j = i - fl * 36;          // (dh*3+dw)*4 + c8
        int g = ((fbase + fl) * 36 + j) * 2;
        Fs[fl * FSTRIDE + j] = cvt_chunk(Fg4[g], Fg4[g + 1]);
    }

    // ---- X fill: 3 rows, swizzled, zero-padded, fp32 -> fp16 ----
    for (int i = tid; i < XS_CH; i += 128) {
        int c8 = i & 3;
        int t = i >> 2;
        int s = t % 36;
        int dh = t / 36;
        int q = s % 9, r = s / 9;
        int wp = 4 * q + r;
        int row = h - 1 + dh;
        int w = wp - 1;
        H2x4 v;
        if (row >= 0 && row < 32 && w >= 0 && w < 32) {
            int g = ((((n * 32) + row) * 32 + w) * 8 + c8 * 2);
            v = cvt_chunk(Xg4[g], Xg4[g + 1]);
        } else {
            __half2 z = __float2half2_rn(0.f);
            v.a = z; v.b = z; v.c = z; v.d = z;
        }
        Xs[(dh * 4 + c8) * 36 + s] = v;
    }
    __syncthreads();

    const int wq = tid & 7;           // pixels w = 4wq .. 4wq+3
    const int fg = tid >> 3;          // 0..15 -> filter fbase + fg

    float2 acc[4];
    #pragma unroll
    for (int p = 0; p < 4; p++) acc[p] = make_float2(0.f, 0.f);

    const H2x4* Fb = Fs + fg * FSTRIDE;

    #pragma unroll
    for (int dh = 0; dh < 3; dh++) {
        // fp16 partial sums for this dh group (4 kk = 48 terms, max ~60: safe)
        __half2 s0, s1, s2, s3;
        #pragma unroll
        for (int c8 = 0; c8 < 4; c8++) {
            const int kk = dh * 4 + c8;
            const int j0 = dh * 12 + c8;

            const H2x4* xr = Xs + kk * 36 + wq;
            H2x4 x0 = xr[0];
            H2x4 x1 = xr[9];
            H2x4 x2 = xr[18];
            H2x4 x3 = xr[27];
            H2x4 x4 = xr[1];
            H2x4 x5 = xr[10];

            H2x4 f0 = Fb[j0], f1 = Fb[j0 + 4], f2 = Fb[j0 + 8];

            __half2 r0 = l1_24(x0, x1, x2, f0, f1, f2);
            __half2 r1 = l1_24(x1, x2, x3, f0, f1, f2);
            __half2 r2 = l1_24(x2, x3, x4, f0, f1, f2);
            __half2 r3 = l1_24(x3, x4, x5, f0, f1, f2);
            if (c8 == 0) {
                s0 = r0; s1 = r1; s2 = r2; s3 = r3;
            } else {
                s0 = __hadd2(s0, r0);
                s1 = __hadd2(s1, r1);
                s2 = __hadd2(s2, r2);
                s3 = __hadd2(s3, r3);
            }
        }
        // fp32 flush once per dh
        float2 t;
        t = __half22float2(s0); acc[0].x += t.x; acc[0].y += t.y;
        t = __half22float2(s1); acc[1].x += t.x; acc[1].y += t.y;
        t = __half22float2(s2); acc[2].x += t.x; acc[2].y += t.y;
        t = __half22float2(s3); acc[3].x += t.x; acc[3].y += t.y;
    }

    // ---- Epilogue: combine packed lanes, scalar store per pixel ----
    float* obase = out + ((nh * 32) + 4 * wq) * 64 + fbase + fg;
    obase[0]   = acc[0].x + acc[0].y;
    obase[64]  = acc[1].x + acc[1].y;
    obase[128] = acc[2].x + acc[2].y;
    obase[192] = acc[3].x + acc[3].y;
}

extern "C" void kernel_launch(void* const* d_in, const int* in_sizes, int n_in,
                              void* d_out, int out_size) {
    const float* X = (const float*)d_in[0];
    const float* Fw = (const float*)d_in[1];
    float* out = (float*)d_out;

    cudaFuncSetAttribute(adder_layer_kernel,
                         cudaFuncAttributeMaxDynamicSharedMemorySize, SMEM_BYTES);
    dim3 grid(256, 4);
    adder_layer_kernel<<<grid, 128, SMEM_BYTES>>>(X, Fw, out);
}